// round 1
// baseline (speedup 1.0000x reference)
#include <cuda_runtime.h>
#include <cstdint>

#define NN 100000
#define F1 256
#define FH 64

// -------- scratch (static device globals; no runtime allocation) --------
__device__ __align__(16) float g_deg[NN];          // degree, then deg^-1/2 in place
__device__ __align__(16) float g_h[NN * FH];       // x@W1+b1
__device__ __align__(16) float g_acc1[NN * FH];    // layer-1 aggregation (pre-relu)
__device__ __align__(16) float g_t[NN * FH];       // relu(acc1)@W2+b2
__device__ __align__(16) float g_acc2[NN * FH];    // z
__device__ int g_is64;

// -------- dtype-agnostic index load (int32 vs int64, decided at runtime) ----
__device__ __forceinline__ long long ldidx(const void* p, long long i) {
    if (g_is64) return ((const long long*)p)[i];
    return (long long)((const int*)p)[i];
}

// Detect whether edge indices are int64 (odd 32-bit words all zero, since
// node ids < 2^17) or int32 (odd words are random node ids).
__global__ void detect_kernel(const unsigned int* p) {
    __shared__ int ok;
    if (threadIdx.x == 0) ok = 1;
    __syncthreads();
    if (p[2 * threadIdx.x + 1] != 0u) atomicExch(&ok, 0);
    __syncthreads();
    if (threadIdx.x == 0) g_is64 = ok;
}

__global__ void zero_kernel(float* p, long long n) {
    long long i = (long long)blockIdx.x * blockDim.x + threadIdx.x;
    long long stride = (long long)gridDim.x * blockDim.x;
    for (; i < n; i += stride) p[i] = 0.0f;
}

__global__ void deg_kernel(const void* pos, long long E, float* deg) {
    long long e = (long long)blockIdx.x * blockDim.x + threadIdx.x;
    if (e >= E) return;
    long long row = ldidx(pos, e);
    atomicAdd(&deg[row], 1.0f);
}

__global__ void dis_kernel(float* deg, int n) {
    int i = blockIdx.x * blockDim.x + threadIdx.x;
    if (i >= n) return;
    float d = deg[i];
    deg[i] = (d > 0.0f) ? rsqrtf(d) : 0.0f;
}

// Y[N,64] = act(X)[N,K] @ W[K,64] + b.  256 threads/block, 64 rows/block.
// Each thread: one row (tid>>2), 16 cols (cq = (tid&3)*16).
__global__ void gemm_kernel(const float* __restrict__ X,
                            const float* __restrict__ W,
                            const float* __restrict__ bias,
                            float* __restrict__ Y,
                            int n, int K, int relu_in) {
    __shared__ float Ws[32 * 64];       // 8 KB  W tile: rows kt..kt+31, cols 0..63
    __shared__ float xs[64 * 36];       // 9 KB  x tile: 64 rows x 32 k (pad 36)

    int tid = threadIdx.x;
    int r = tid >> 2;
    int cq = (tid & 3) * 16;
    long long row0 = (long long)blockIdx.x * 64;

    float acc[16];
#pragma unroll
    for (int j = 0; j < 16; j++) acc[j] = 0.0f;

    for (int kt = 0; kt < K; kt += 32) {
        // W tile: 2048 floats = 512 float4, 2 per thread
        const float4* Wv = (const float4*)(W + (long long)kt * 64);
        float4* Wsv = (float4*)Ws;
        Wsv[tid] = Wv[tid];
        Wsv[tid + 256] = Wv[tid + 256];
        // X tile: 64 rows x 8 float4, 2 per thread
#pragma unroll
        for (int rep = 0; rep < 2; rep++) {
            int idx = tid + rep * 256;
            int rr = idx >> 3;
            int kk4 = idx & 7;
            long long row = row0 + rr;
            float4 v = make_float4(0.f, 0.f, 0.f, 0.f);
            if (row < n)
                v = *(const float4*)(X + row * K + kt + kk4 * 4);
            if (relu_in) {
                v.x = fmaxf(v.x, 0.f); v.y = fmaxf(v.y, 0.f);
                v.z = fmaxf(v.z, 0.f); v.w = fmaxf(v.w, 0.f);
            }
            *(float4*)(xs + rr * 36 + kk4 * 4) = v;
        }
        __syncthreads();

#pragma unroll
        for (int k = 0; k < 32; k++) {
            float xv = xs[r * 36 + k];
            const float4* wr = (const float4*)(Ws + k * 64 + cq);
            float4 w0 = wr[0], w1 = wr[1], w2 = wr[2], w3 = wr[3];
            acc[0]  += xv * w0.x;  acc[1]  += xv * w0.y;
            acc[2]  += xv * w0.z;  acc[3]  += xv * w0.w;
            acc[4]  += xv * w1.x;  acc[5]  += xv * w1.y;
            acc[6]  += xv * w1.z;  acc[7]  += xv * w1.w;
            acc[8]  += xv * w2.x;  acc[9]  += xv * w2.y;
            acc[10] += xv * w2.z;  acc[11] += xv * w2.w;
            acc[12] += xv * w3.x;  acc[13] += xv * w3.y;
            acc[14] += xv * w3.w == 0.f ? xv * w3.z : xv * w3.z;  // (see below)
            acc[15] += xv * w3.w;
        }
        __syncthreads();
    }

    long long row = row0 + r;
    if (row < n) {
        float* yp = Y + row * 64 + cq;
#pragma unroll
        for (int q = 0; q < 4; q++) {
            float4 o;
            o.x = acc[q * 4 + 0] + bias[cq + q * 4 + 0];
            o.y = acc[q * 4 + 1] + bias[cq + q * 4 + 1];
            o.z = acc[q * 4 + 2] + bias[cq + q * 4 + 2];
            o.w = acc[q * 4 + 3] + bias[cq + q * 4 + 3];
            *(float4*)(yp + q * 4) = o;
        }
    }
}

// Edge scatter: 16 threads per edge, float4 per thread, vector red.
__global__ void scatter_kernel(const void* eidx, long long E,
                               const float* __restrict__ dis,
                               const float* __restrict__ H,
                               float* __restrict__ Acc) {
    long long t = (long long)blockIdx.x * blockDim.x + threadIdx.x;
    long long e = t >> 4;
    if (e >= E) return;
    int lane = threadIdx.x & 31;
    int j = lane & 15;
    int leader = lane & 16;     // leader lane of this 16-thread group

    long long row = 0, col = 0;
    float norm = 0.0f;
    if (j == 0) {
        row = ldidx(eidx, e);
        col = ldidx(eidx, E + e);
        norm = dis[row] * dis[col];
    }
    row = __shfl_sync(0xffffffffu, row, leader);
    col = __shfl_sync(0xffffffffu, col, leader);
    norm = __shfl_sync(0xffffffffu, norm, leader);

    if (norm != 0.0f) {
        float4 hv = __ldg(((const float4*)H) + col * 16 + j);
        float vx = norm * hv.x, vy = norm * hv.y, vz = norm * hv.z, vw = norm * hv.w;
        float* addr = Acc + row * 64 + j * 4;
        asm volatile("red.global.add.v4.f32 [%0], {%1, %2, %3, %4};"
                     :: "l"(addr), "f"(vx), "f"(vy), "f"(vz), "f"(vw)
                     : "memory");
    }
}

// Decode: one warp per output edge. out[e] = dot(z[a], z[b]) over 64 dims.
__global__ void decode_kernel(const void* pos, const void* neg, long long E,
                              const float* __restrict__ Z, float* __restrict__ out) {
    long long w = ((long long)blockIdx.x * blockDim.x + threadIdx.x) >> 5;
    if (w >= 2 * E) return;
    int lane = threadIdx.x & 31;

    long long a = 0, b = 0;
    if (lane == 0) {
        if (w < E) { a = ldidx(pos, w);     b = ldidx(pos, E + w); }
        else       { long long e = w - E;
                     a = ldidx(neg, e);     b = ldidx(neg, E + e); }
    }
    a = __shfl_sync(0xffffffffu, a, 0);
    b = __shfl_sync(0xffffffffu, b, 0);

    float2 za = __ldg(((const float2*)Z) + a * 32 + lane);
    float2 zb = __ldg(((const float2*)Z) + b * 32 + lane);
    float s = za.x * zb.x + za.y * zb.y;
#pragma unroll
    for (int off = 16; off; off >>= 1)
        s += __shfl_xor_sync(0xffffffffu, s, off);
    if (lane == 0) out[w] = s;
}

extern "C" void kernel_launch(void* const* d_in, const int* in_sizes, int n_in,
                              void* d_out, int out_size) {
    const float* x  = (const float*)d_in[0];
    const void*  pos = d_in[1];
    const void*  neg = d_in[2];
    const float* W1 = (const float*)d_in[3];
    const float* b1 = (const float*)d_in[4];
    const float* W2 = (const float*)d_in[5];
    const float* b2 = (const float*)d_in[6];
    float* out = (float*)d_out;

    long long E = (long long)in_sizes[1] / 2;   // 1.6M
    int n = NN;
    int Fin = in_sizes[0] / n;                  // 256

    float *deg, *h, *acc1, *t, *acc2;
    cudaGetSymbolAddress((void**)&deg,  g_deg);
    cudaGetSymbolAddress((void**)&h,    g_h);
    cudaGetSymbolAddress((void**)&acc1, g_acc1);
    cudaGetSymbolAddress((void**)&t,    g_t);
    cudaGetSymbolAddress((void**)&acc2, g_acc2);

    detect_kernel<<<1, 64>>>((const unsigned int*)pos);

    zero_kernel<<<1024, 256>>>(deg, (long long)n);
    zero_kernel<<<4096, 256>>>(acc1, (long long)n * 64);
    zero_kernel<<<4096, 256>>>(acc2, (long long)n * 64);

    deg_kernel<<<(int)((E + 255) / 256), 256>>>(pos, E, deg);
    dis_kernel<<<(n + 255) / 256, 256>>>(deg, n);

    int gblocks = (n + 63) / 64;
    gemm_kernel<<<gblocks, 256>>>(x, W1, b1, h, n, Fin, 0);

    int sblocks = (int)((E * 16 + 255) / 256);
    scatter_kernel<<<sblocks, 256>>>(pos, E, deg, h, acc1);

    gemm_kernel<<<gblocks, 256>>>(acc1, W2, b2, t, n, 64, 1);
    scatter_kernel<<<sblocks, 256>>>(pos, E, deg, t, acc2);

    int dblocks = (int)((2 * E * 32 + 255) / 256);
    decode_kernel<<<dblocks, 256>>>(pos, neg, E, acc2, out);
}